// round 16
// baseline (speedup 1.0000x reference)
#include <cuda_runtime.h>
#include <cstdint>
#include <math.h>

#define Bb   8
#define LEAF 1024
#define Nn   2048
#define Dd   128
#define BN   (Bb * Nn)      // 16384
#define HEAVY_PER_B 15      // locals 1..15 have deg > 128
#define HCHUNKS 16          // 16 chunks x 128 edges covers deg <= 2046
#define HEAVY_W (Bb * HEAVY_PER_B * HCHUNKS)   // 1920

// Scratch (allocation-free rule: device globals)
__device__ float g_nf  [BN * Dd];          // raw node features (tree means, nodes >= 32)
__device__ float g_h   [BN * Dd];          // gelu(LN(x))
__device__ float g_agg [BN * Dd];          // mean aggregation
__device__ float g_part[HEAVY_W * Dd];     // heavy-node partial sums
__device__ int   g_off [BN + 1];           // CSR offsets into edge list

// ---------------------------------------------------------------------------
// f32x2 packed helpers (SASS FFMA2 — PTX-only)
// ---------------------------------------------------------------------------
__device__ __forceinline__ unsigned long long pack2(float lo, float hi) {
    unsigned long long r;
    asm("mov.b64 %0, {%1, %2};" : "=l"(r) : "f"(lo), "f"(hi));
    return r;
}
__device__ __forceinline__ void unpack2(unsigned long long v, float& lo, float& hi) {
    asm("mov.b64 {%0, %1}, %2;" : "=f"(lo), "=f"(hi) : "l"(v));
}
__device__ __forceinline__ void ffma2(unsigned long long& d,
                                      unsigned long long a,
                                      unsigned long long b) {
    asm("fma.rn.f32x2 %0, %1, %2, %0;" : "+l"(d) : "l"(a), "l"(b));
}
__device__ __forceinline__ void cp_async16(uint32_t smem_addr, const void* gptr) {
    asm volatile("cp.async.cg.shared.global [%0], [%1], 16;"
                 :: "r"(smem_addr), "l"(gptr) : "memory");
}
__device__ __forceinline__ void cp_commit() {
    asm volatile("cp.async.commit_group;" ::: "memory");
}
__device__ __forceinline__ void cp_wait0() {
    asm volatile("cp.async.wait_group 0;" ::: "memory");
}

// ---------------------------------------------------------------------------
// Launch 1: blocks [0,256): tree up-sweep for levels 10..5 (one 32-leaf
// subtree per block); blocks [256,..): edge-parallel CSR offsets.
// ---------------------------------------------------------------------------
__global__ void tree1off_kernel(const float* __restrict__ elements,
                                const int* __restrict__ dst, int E) {
    if (blockIdx.x < 256) {
        int d = threadIdx.x;
        if (d >= Dd) return;
        int b = blockIdx.x >> 5;
        int s = blockIdx.x & 31;
        int bN = b * Nn;
        float v32[32];
#pragma unroll
        for (int j = 0; j < 32; j++) {
            float v = elements[(b * LEAF + s * 32 + j) * Dd + d];
            v32[j] = v;
            g_nf[(bN + LEAF + s * 32 + j) * Dd + d] = v;
        }
        float v16[16];
#pragma unroll
        for (int j = 0; j < 16; j++) {
            v16[j] = 0.5f * (v32[2*j] + v32[2*j+1]);
            g_nf[(bN + 512 + s * 16 + j) * Dd + d] = v16[j];
        }
        float v8[8];
#pragma unroll
        for (int j = 0; j < 8; j++) {
            v8[j] = 0.5f * (v16[2*j] + v16[2*j+1]);
            g_nf[(bN + 256 + s * 8 + j) * Dd + d] = v8[j];
        }
        float v4[4];
#pragma unroll
        for (int j = 0; j < 4; j++) {
            v4[j] = 0.5f * (v8[2*j] + v8[2*j+1]);
            g_nf[(bN + 128 + s * 4 + j) * Dd + d] = v4[j];
        }
        float v2[2];
#pragma unroll
        for (int j = 0; j < 2; j++) {
            v2[j] = 0.5f * (v4[2*j] + v4[2*j+1]);
            g_nf[(bN + 64 + s * 2 + j) * Dd + d] = v2[j];
        }
        g_nf[(bN + 32 + s) * Dd + d] = 0.5f * (v2[0] + v2[1]);
        return;
    }
    int e = (blockIdx.x - 256) * 256 + threadIdx.x;
    if (e >= E) return;
    int d1 = dst[e];
    int d0 = (e == 0) ? -1 : dst[e - 1];
    for (int i = d0 + 1; i <= d1; i++) g_off[i] = e;
    if (e == E - 1)
        for (int i = d1 + 1; i <= BN; i++) g_off[i] = E;
}

// ---------------------------------------------------------------------------
// Launch 2: x = nf + positional encoding; fused LN + exact GELU -> g_h.
// ---------------------------------------------------------------------------
__global__ void encx2_kernel(float* __restrict__ x,
                             const float* __restrict__ gamma,
                             const float* __restrict__ beta) {
    int gi = blockIdx.x;
    int node = gi & (Nn - 1);
    int d = threadIdx.x;

    float nfv;
    if (node == 0) {
        nfv = -1.0f;
    } else if (node < 32) {
        int lvl = 31 - __clz(node);
        int c = 1 << (5 - lvl);
        int start = node << (5 - lvl);
        const float* base = &g_nf[(gi - node + start) * Dd + d];
        float sum = 0.f;
        for (int j = 0; j < c; j++) sum += base[j * Dd];
        nfv = sum * (1.0f / (float)c);
    } else {
        nfv = g_nf[gi * Dd + d];
    }

    float pos;
    if (node == 0) {
        pos = (d < 64) ? -0.5f : -1.0f;
    } else {
        int vp = 31 - __clz(node);
        pos = (d < 64) ? (float)(node - (1 << vp)) : (float)vp;
    }
    int dd = d & 63;
    int k = dd >> 1;
    float inv = expf(-0.28782313662425574f * (float)k);   // exp(-k*ln(1e4)/32)
    float ang = pos * inv;
    float e = (dd & 1) ? cosf(ang) : sinf(ang);
    float v = nfv + e;
    x[gi * Dd + d] = v;

    float s = v, s2 = v * v;
#pragma unroll
    for (int o = 16; o; o >>= 1) {
        s  += __shfl_xor_sync(0xffffffffu, s, o);
        s2 += __shfl_xor_sync(0xffffffffu, s2, o);
    }
    __shared__ float ss[4], ss2[4];
    int w = d >> 5, lane = d & 31;
    if (lane == 0) { ss[w] = s; ss2[w] = s2; }
    __syncthreads();
    s  = ss[0] + ss[1] + ss[2] + ss[3];
    s2 = ss2[0] + ss2[1] + ss2[2] + ss2[3];
    float mu  = s * (1.0f / 128.0f);
    float var = s2 * (1.0f / 128.0f) - mu * mu;
    float t = (v - mu) * rsqrtf(var + 1e-5f) * gamma[d] + beta[d];
    g_h[gi * Dd + d] = 0.5f * t * (1.0f + erff(t * 0.70710678118654752f));
}

// ---------------------------------------------------------------------------
// Aggregation (r14 champion version: 4 rows in flight)
// ---------------------------------------------------------------------------
__global__ void agg_kernel(const int* __restrict__ src) {
    __shared__ __align__(16) float sbuf[4 * Dd];
    int bid = blockIdx.x;
    int tid = threadIdx.x;
    int g = tid >> 5, l = tid & 31;
    int s, e;
    float scale;
    float* out;
    if (bid < BN) {
        int i = bid;
        int local = i & (Nn - 1);
        if (local >= 1 && local <= HEAVY_PER_B) return;   // gemm prologue handles
        s = g_off[i];
        e = g_off[i + 1];
        int deg = e - s;
        scale = 1.0f / (float)(deg > 0 ? deg : 1);
        out = &g_agg[i * Dd];
    } else {
        int w = bid - BN;
        int b = w / (HEAVY_PER_B * HCHUNKS);
        int r = w % (HEAVY_PER_B * HCHUNKS);
        int local = 1 + (r >> 4);
        int c = r & 15;
        int i = b * Nn + local;
        int s0 = g_off[i], e0 = g_off[i + 1];
        s = s0 + c * 128;
        e = min(e0, s + 128);
        if (e < s) e = s;
        scale = 1.0f;
        out = &g_part[w * Dd];
    }
    float4 acc = make_float4(0.f, 0.f, 0.f, 0.f);
    int t = s + g;
    for (; t + 12 < e; t += 16) {
        int i0 = __ldg(&src[t]);
        int i1 = __ldg(&src[t + 4]);
        int i2 = __ldg(&src[t + 8]);
        int i3 = __ldg(&src[t + 12]);
        float4 v0 = *(const float4*)&g_h[i0 * Dd + l * 4];
        float4 v1 = *(const float4*)&g_h[i1 * Dd + l * 4];
        float4 v2 = *(const float4*)&g_h[i2 * Dd + l * 4];
        float4 v3 = *(const float4*)&g_h[i3 * Dd + l * 4];
        acc.x += (v0.x + v1.x) + (v2.x + v3.x);
        acc.y += (v0.y + v1.y) + (v2.y + v3.y);
        acc.z += (v0.z + v1.z) + (v2.z + v3.z);
        acc.w += (v0.w + v1.w) + (v2.w + v3.w);
    }
    for (; t < e; t += 4) {
        int i0 = __ldg(&src[t]);
        float4 v0 = *(const float4*)&g_h[i0 * Dd + l * 4];
        acc.x += v0.x; acc.y += v0.y; acc.z += v0.z; acc.w += v0.w;
    }
    *(float4*)&sbuf[g * Dd + l * 4] = acc;
    __syncthreads();
    float v = sbuf[tid] + sbuf[Dd + tid] + sbuf[2 * Dd + tid] + sbuf[3 * Dd + tid];
    out[tid] = v * scale;
}

// ---------------------------------------------------------------------------
// x += agg @ W1 + bias + h @ W2 — double-buffered pipelined FFMA2 GEMM.
// r14 structure, but 256 threads splitting the BM=64 tile by M:
// micro-tile 4x8 (acc 32 regs), per kk: 4 LDS.128 + 16 FFMA2.
// Same grid (256), same traffic, same barrier count — 2x warps/SM to hide
// the LDS/pipeline latency that kept issue at 14%.
// Prologue: block owning rows (bm%2048)==0 finalizes 15 heavy agg rows.
// FUSE: epilogue computes next layer's h = gelu(LN(x_new)) into g_h.
// ---------------------------------------------------------------------------
template<bool FUSE>
__global__ void __launch_bounds__(256) gemm_kernel(
    const float* __restrict__ W1, const float* __restrict__ W2,
    const float* __restrict__ bias,
    const float* __restrict__ gamma, const float* __restrict__ beta,
    float* __restrict__ X)
{
    __shared__ __align__(16) unsigned long long As2[2][16][64]; // 16 KB, (a,a) pairs
    __shared__ __align__(16) float Bs[2][16][128];               // 16 KB
    const int bm = blockIdx.x * 64;
    const int tid = threadIdx.x;
    const int trow = tid >> 4;   // 0..15
    const int tcol = tid & 15;   // 0..15
    const int tm = trow * 4;     // 0..60
    const int tn = tcol * 8;

    // heavy-row fixup (aggfix folded in): one block per batch chunk
    if ((bm & (Nn - 1)) == 0) {
        int b = bm / Nn;
        for (int e = tid; e < HEAVY_PER_B * Dd; e += 256) {
            int r = e >> 7;          // 0..14, local = r+1
            int col = e & 127;
            float sum = 0.f;
#pragma unroll
            for (int c = 0; c < HCHUNKS; c++)
                sum += g_part[((b * HEAVY_PER_B + r) * HCHUNKS + c) * Dd + col];
            int i = bm + 1 + r;
            int deg = g_off[i + 1] - g_off[i];
            g_agg[i * Dd + col] = sum / (float)deg;
        }
        __syncthreads();
    }

    unsigned long long acc[4][4];
#pragma unroll
    for (int i = 0; i < 4; i++)
#pragma unroll
        for (int j = 0; j < 4; j++) acc[i][j] = 0ull;

    // load assignments (256 threads)
    const int mA = tid >> 2;          // 0..63 (A row)
    const int qA = tid & 3;           // 0..3: cols qA*4 .. qA*4+3 (of 16)
    const int rB = tid >> 4;          // 0..15 (B row)
    const int cB = (tid & 15) * 8;    // B col base (8 floats)

    // tile it (0..15): pass = it>>3, k0 = (it&7)*16
    // --- prologue: tile 0 into buffer 0 ---
    {
        float4 v = *(const float4*)&g_agg[(bm + mA) * Dd + qA * 4];
        int kb = qA * 4;
        As2[0][kb + 0][mA] = pack2(v.x, v.x);
        As2[0][kb + 1][mA] = pack2(v.y, v.y);
        As2[0][kb + 2][mA] = pack2(v.z, v.z);
        As2[0][kb + 3][mA] = pack2(v.w, v.w);
        uint32_t bdst = (uint32_t)__cvta_generic_to_shared(&Bs[0][rB][cB]);
        const float* wp = &W1[rB * Dd + cB];
        cp_async16(bdst, wp);
        cp_async16(bdst + 16, wp + 4);
        cp_commit();
        cp_wait0();
    }
    __syncthreads();

#pragma unroll
    for (int it = 0; it < 16; it++) {
        const int cur = it & 1;
        const int nxt = cur ^ 1;

        // kick loads for tile it+1
        float4 av;
        if (it < 15) {
            const int nit = it + 1;
            const float* Ap = (nit >= 8) ? (const float*)g_h : (const float*)g_agg;
            const float* Wp = (nit >= 8) ? W2 : W1;
            const int k0 = (nit & 7) * 16;
            av = *(const float4*)&Ap[(bm + mA) * Dd + k0 + qA * 4];
            uint32_t bdst = (uint32_t)__cvta_generic_to_shared(&Bs[nxt][rB][cB]);
            const float* wp = &Wp[(k0 + rB) * Dd + cB];
            cp_async16(bdst, wp);
            cp_async16(bdst + 16, wp + 4);
            cp_commit();
        }

        // compute tile it
#pragma unroll
        for (int kk = 0; kk < 16; kk++) {
            ulonglong2 p01 = *(const ulonglong2*)&As2[cur][kk][tm];
            ulonglong2 p23 = *(const ulonglong2*)&As2[cur][kk][tm + 2];
            ulonglong2 b01 = *(const ulonglong2*)&Bs[cur][kk][tn];
            ulonglong2 b23 = *(const ulonglong2*)&Bs[cur][kk][tn + 4];
            unsigned long long ap[4] = {p01.x, p01.y, p23.x, p23.y};
            unsigned long long bp[4] = {b01.x, b01.y, b23.x, b23.y};
#pragma unroll
            for (int i = 0; i < 4; i++) {
                ffma2(acc[i][0], ap[i], bp[0]);
                ffma2(acc[i][1], ap[i], bp[1]);
                ffma2(acc[i][2], ap[i], bp[2]);
                ffma2(acc[i][3], ap[i], bp[3]);
            }
        }

        // stage A for tile it+1, drain B cp.async, flip
        if (it < 15) {
            int kb = qA * 4;
            As2[nxt][kb + 0][mA] = pack2(av.x, av.x);
            As2[nxt][kb + 1][mA] = pack2(av.y, av.y);
            As2[nxt][kb + 2][mA] = pack2(av.z, av.z);
            As2[nxt][kb + 3][mA] = pack2(av.w, av.w);
            cp_wait0();
        }
        __syncthreads();
    }

    // Epilogue
    float bb[8], gg[8], be[8];
#pragma unroll
    for (int j = 0; j < 8; j++) bb[j] = bias[tn + j];
    if (FUSE) {
#pragma unroll
        for (int j = 0; j < 8; j++) { gg[j] = gamma[tn + j]; be[j] = beta[tn + j]; }
    }
#pragma unroll
    for (int i = 0; i < 4; i++) {
        int row = bm + tm + i;
        float4 x0 = *(const float4*)&X[row * Dd + tn];
        float4 x1 = *(const float4*)&X[row * Dd + tn + 4];
        float xv[8] = {x0.x, x0.y, x0.z, x0.w, x1.x, x1.y, x1.z, x1.w};
#pragma unroll
        for (int j = 0; j < 4; j++) {
            float lo, hi;
            unpack2(acc[i][j], lo, hi);
            xv[2*j]   += lo + bb[2*j];
            xv[2*j+1] += hi + bb[2*j+1];
        }
        x0 = make_float4(xv[0], xv[1], xv[2], xv[3]);
        x1 = make_float4(xv[4], xv[5], xv[6], xv[7]);
        *(float4*)&X[row * Dd + tn]     = x0;
        *(float4*)&X[row * Dd + tn + 4] = x1;
        if (FUSE) {
            float s = 0.f, s2 = 0.f;
#pragma unroll
            for (int j = 0; j < 8; j++) { s += xv[j]; s2 += xv[j] * xv[j]; }
#pragma unroll
            for (int o = 1; o <= 8; o <<= 1) {
                s  += __shfl_xor_sync(0xffffffffu, s, o);
                s2 += __shfl_xor_sync(0xffffffffu, s2, o);
            }
            float mu  = s * (1.0f / 128.0f);
            float var = s2 * (1.0f / 128.0f) - mu * mu;
            float rs  = rsqrtf(var + 1e-5f);
            float hv[8];
#pragma unroll
            for (int j = 0; j < 8; j++) {
                float t = (xv[j] - mu) * rs * gg[j] + be[j];
                hv[j] = 0.5f * t * (1.0f + erff(t * 0.70710678118654752f));
            }
            *(float4*)&g_h[row * Dd + tn]     = make_float4(hv[0], hv[1], hv[2], hv[3]);
            *(float4*)&g_h[row * Dd + tn + 4] = make_float4(hv[4], hv[5], hv[6], hv[7]);
        }
    }
}

// ---------------------------------------------------------------------------
extern "C" void kernel_launch(void* const* d_in, const int* in_sizes, int n_in,
                              void* d_out, int out_size) {
    const float* elements = (const float*)d_in[0];
    const float* ln_gamma = (const float*)d_in[1];
    const float* ln_beta  = (const float*)d_in[2];
    const float* w_nei    = (const float*)d_in[3];
    const float* b_nei    = (const float*)d_in[4];
    const float* w_root   = (const float*)d_in[5];
    const int*   edges    = (const int*)d_in[6];
    float* x = (float*)d_out;

    int E = in_sizes[6] / 2;
    const int* src = edges;
    const int* dst = edges + E;

    tree1off_kernel<<<256 + (E + 255) / 256, 256>>>(elements, dst, E);   // 1
    encx2_kernel<<<BN, Dd>>>(x, ln_gamma, ln_beta);                      // 2

    // layer 0
    agg_kernel<<<BN + HEAVY_W, Dd>>>(src);                               // 3
    gemm_kernel<true><<<BN / 64, 256>>>(w_nei, w_root, b_nei,
                                        ln_gamma + Dd, ln_beta + Dd, x); // 4 (profiled)

    // layer 1 (final — no fused LN)
    agg_kernel<<<BN + HEAVY_W, Dd>>>(src);                               // 5
    gemm_kernel<false><<<BN / 64, 256>>>(w_nei + Dd * Dd, w_root + Dd * Dd,
                                         b_nei + Dd, nullptr, nullptr, x); // 6
}

// round 17
// speedup vs baseline: 1.2473x; 1.2473x over previous
#include <cuda_runtime.h>
#include <cstdint>
#include <math.h>

#define Bb   8
#define LEAF 1024
#define Nn   2048
#define Dd   128
#define BN   (Bb * Nn)      // 16384
#define HEAVY_PER_B 15      // locals 1..15 have deg > 128
#define HCHUNKS 16          // 16 chunks x 128 edges covers deg <= 2046
#define HEAVY_W (Bb * HEAVY_PER_B * HCHUNKS)   // 1920

// Scratch (allocation-free rule: device globals)
__device__ float g_nf  [BN * Dd];          // raw node features (tree means, nodes >= 32)
__device__ float g_h   [BN * Dd];          // gelu(LN(x))
__device__ float g_agg [BN * Dd];          // mean aggregation
__device__ float g_part[HEAVY_W * Dd];     // heavy-node partial sums
__device__ int   g_off [BN + 1];           // CSR offsets into edge list

// ---------------------------------------------------------------------------
// f32x2 packed helpers (SASS FFMA2 — PTX-only)
// ---------------------------------------------------------------------------
__device__ __forceinline__ unsigned long long pack2s(float a) {
    unsigned long long r;
    asm("mov.b64 %0, {%1, %1};" : "=l"(r) : "f"(a));
    return r;
}
__device__ __forceinline__ void unpack2(unsigned long long v, float& lo, float& hi) {
    asm("mov.b64 {%0, %1}, %2;" : "=f"(lo), "=f"(hi) : "l"(v));
}
__device__ __forceinline__ void ffma2(unsigned long long& d,
                                      unsigned long long a,
                                      unsigned long long b) {
    asm("fma.rn.f32x2 %0, %1, %2, %0;" : "+l"(d) : "l"(a), "l"(b));
}
__device__ __forceinline__ void cp_async16(uint32_t smem_addr, const void* gptr) {
    asm volatile("cp.async.cg.shared.global [%0], [%1], 16;"
                 :: "r"(smem_addr), "l"(gptr) : "memory");
}
__device__ __forceinline__ void cp_commit() {
    asm volatile("cp.async.commit_group;" ::: "memory");
}
__device__ __forceinline__ void cp_wait0() {
    asm volatile("cp.async.wait_group 0;" ::: "memory");
}

// ---------------------------------------------------------------------------
// Launch 1: blocks [0,256): tree up-sweep for levels 10..5 (one 32-leaf
// subtree per block); blocks [256,..): edge-parallel CSR offsets.
// ---------------------------------------------------------------------------
__global__ void tree1off_kernel(const float* __restrict__ elements,
                                const int* __restrict__ dst, int E) {
    if (blockIdx.x < 256) {
        int d = threadIdx.x;
        if (d >= Dd) return;
        int b = blockIdx.x >> 5;
        int s = blockIdx.x & 31;
        int bN = b * Nn;
        float v32[32];
#pragma unroll
        for (int j = 0; j < 32; j++) {
            float v = elements[(b * LEAF + s * 32 + j) * Dd + d];
            v32[j] = v;
            g_nf[(bN + LEAF + s * 32 + j) * Dd + d] = v;
        }
        float v16[16];
#pragma unroll
        for (int j = 0; j < 16; j++) {
            v16[j] = 0.5f * (v32[2*j] + v32[2*j+1]);
            g_nf[(bN + 512 + s * 16 + j) * Dd + d] = v16[j];
        }
        float v8[8];
#pragma unroll
        for (int j = 0; j < 8; j++) {
            v8[j] = 0.5f * (v16[2*j] + v16[2*j+1]);
            g_nf[(bN + 256 + s * 8 + j) * Dd + d] = v8[j];
        }
        float v4[4];
#pragma unroll
        for (int j = 0; j < 4; j++) {
            v4[j] = 0.5f * (v8[2*j] + v8[2*j+1]);
            g_nf[(bN + 128 + s * 4 + j) * Dd + d] = v4[j];
        }
        float v2[2];
#pragma unroll
        for (int j = 0; j < 2; j++) {
            v2[j] = 0.5f * (v4[2*j] + v4[2*j+1]);
            g_nf[(bN + 64 + s * 2 + j) * Dd + d] = v2[j];
        }
        g_nf[(bN + 32 + s) * Dd + d] = 0.5f * (v2[0] + v2[1]);
        return;
    }
    int e = (blockIdx.x - 256) * 256 + threadIdx.x;
    if (e >= E) return;
    int d1 = dst[e];
    int d0 = (e == 0) ? -1 : dst[e - 1];
    for (int i = d0 + 1; i <= d1; i++) g_off[i] = e;
    if (e == E - 1)
        for (int i = d1 + 1; i <= BN; i++) g_off[i] = E;
}

// ---------------------------------------------------------------------------
// Launch 2: x = nf + positional encoding; fused LN + exact GELU -> g_h.
// ---------------------------------------------------------------------------
__global__ void encx2_kernel(float* __restrict__ x,
                             const float* __restrict__ gamma,
                             const float* __restrict__ beta) {
    int gi = blockIdx.x;
    int node = gi & (Nn - 1);
    int d = threadIdx.x;

    float nfv;
    if (node == 0) {
        nfv = -1.0f;
    } else if (node < 32) {
        int lvl = 31 - __clz(node);
        int c = 1 << (5 - lvl);
        int start = node << (5 - lvl);
        const float* base = &g_nf[(gi - node + start) * Dd + d];
        float sum = 0.f;
        for (int j = 0; j < c; j++) sum += base[j * Dd];
        nfv = sum * (1.0f / (float)c);
    } else {
        nfv = g_nf[gi * Dd + d];
    }

    float pos;
    if (node == 0) {
        pos = (d < 64) ? -0.5f : -1.0f;
    } else {
        int vp = 31 - __clz(node);
        pos = (d < 64) ? (float)(node - (1 << vp)) : (float)vp;
    }
    int dd = d & 63;
    int k = dd >> 1;
    float inv = expf(-0.28782313662425574f * (float)k);   // exp(-k*ln(1e4)/32)
    float ang = pos * inv;
    float e = (dd & 1) ? cosf(ang) : sinf(ang);
    float v = nfv + e;
    x[gi * Dd + d] = v;

    float s = v, s2 = v * v;
#pragma unroll
    for (int o = 16; o; o >>= 1) {
        s  += __shfl_xor_sync(0xffffffffu, s, o);
        s2 += __shfl_xor_sync(0xffffffffu, s2, o);
    }
    __shared__ float ss[4], ss2[4];
    int w = d >> 5, lane = d & 31;
    if (lane == 0) { ss[w] = s; ss2[w] = s2; }
    __syncthreads();
    s  = ss[0] + ss[1] + ss[2] + ss[3];
    s2 = ss2[0] + ss2[1] + ss2[2] + ss2[3];
    float mu  = s * (1.0f / 128.0f);
    float var = s2 * (1.0f / 128.0f) - mu * mu;
    float t = (v - mu) * rsqrtf(var + 1e-5f) * gamma[d] + beta[d];
    g_h[gi * Dd + d] = 0.5f * t * (1.0f + erff(t * 0.70710678118654752f));
}

// ---------------------------------------------------------------------------
// Aggregation (r14 champion version: 4 rows in flight)
// ---------------------------------------------------------------------------
__global__ void agg_kernel(const int* __restrict__ src) {
    __shared__ __align__(16) float sbuf[4 * Dd];
    int bid = blockIdx.x;
    int tid = threadIdx.x;
    int g = tid >> 5, l = tid & 31;
    int s, e;
    float scale;
    float* out;
    if (bid < BN) {
        int i = bid;
        int local = i & (Nn - 1);
        if (local >= 1 && local <= HEAVY_PER_B) return;   // gemm prologue handles
        s = g_off[i];
        e = g_off[i + 1];
        int deg = e - s;
        scale = 1.0f / (float)(deg > 0 ? deg : 1);
        out = &g_agg[i * Dd];
    } else {
        int w = bid - BN;
        int b = w / (HEAVY_PER_B * HCHUNKS);
        int r = w % (HEAVY_PER_B * HCHUNKS);
        int local = 1 + (r >> 4);
        int c = r & 15;
        int i = b * Nn + local;
        int s0 = g_off[i], e0 = g_off[i + 1];
        s = s0 + c * 128;
        e = min(e0, s + 128);
        if (e < s) e = s;
        scale = 1.0f;
        out = &g_part[w * Dd];
    }
    float4 acc = make_float4(0.f, 0.f, 0.f, 0.f);
    int t = s + g;
    for (; t + 12 < e; t += 16) {
        int i0 = __ldg(&src[t]);
        int i1 = __ldg(&src[t + 4]);
        int i2 = __ldg(&src[t + 8]);
        int i3 = __ldg(&src[t + 12]);
        float4 v0 = *(const float4*)&g_h[i0 * Dd + l * 4];
        float4 v1 = *(const float4*)&g_h[i1 * Dd + l * 4];
        float4 v2 = *(const float4*)&g_h[i2 * Dd + l * 4];
        float4 v3 = *(const float4*)&g_h[i3 * Dd + l * 4];
        acc.x += (v0.x + v1.x) + (v2.x + v3.x);
        acc.y += (v0.y + v1.y) + (v2.y + v3.y);
        acc.z += (v0.z + v1.z) + (v2.z + v3.z);
        acc.w += (v0.w + v1.w) + (v2.w + v3.w);
    }
    for (; t < e; t += 4) {
        int i0 = __ldg(&src[t]);
        float4 v0 = *(const float4*)&g_h[i0 * Dd + l * 4];
        acc.x += v0.x; acc.y += v0.y; acc.z += v0.z; acc.w += v0.w;
    }
    *(float4*)&sbuf[g * Dd + l * 4] = acc;
    __syncthreads();
    float v = sbuf[tid] + sbuf[Dd + tid] + sbuf[2 * Dd + tid] + sbuf[3 * Dd + tid];
    out[tid] = v * scale;
}

// ---------------------------------------------------------------------------
// x += agg @ W1 + bias + h @ W2 — double-buffered pipelined FFMA2 GEMM.
// r14 pipeline structure; A stored PLAIN in smem (no dup pairs), (a,a)
// built in-loop with mov.b64 {a,a} (1 reg, ALU pipe). Per kk/thread:
// A 2xLDS.128 + B 2xLDS.128 = 64B per 32 FFMA2 = 2 B/FFMA2 — LDS floor
// halves from r14's 3 B/FFMA2. 8 MOVs/kk ride the idle ALU pipe.
// Prologue: block owning rows (bm%2048)==0 finalizes 15 heavy agg rows.
// FUSE: epilogue computes next layer's h = gelu(LN(x_new)) into g_h.
// ---------------------------------------------------------------------------
template<bool FUSE>
__global__ void __launch_bounds__(128) gemm_kernel(
    const float* __restrict__ W1, const float* __restrict__ W2,
    const float* __restrict__ bias,
    const float* __restrict__ gamma, const float* __restrict__ beta,
    float* __restrict__ X)
{
    __shared__ __align__(16) float As[2][16][64];    // 8 KB, plain floats
    __shared__ __align__(16) float Bs[2][16][128];   // 16 KB
    const int bm = blockIdx.x * 64;
    const int tid = threadIdx.x;
    const int trow = tid >> 4;   // 0..7
    const int tcol = tid & 15;   // 0..15
    const int tm = trow * 8;
    const int tn = tcol * 8;

    // heavy-row fixup (aggfix folded in): one block per batch chunk
    if ((bm & (Nn - 1)) == 0) {
        int b = bm / Nn;
        for (int e = tid; e < HEAVY_PER_B * Dd; e += 128) {
            int r = e >> 7;          // 0..14, local = r+1
            int col = e & 127;
            float sum = 0.f;
#pragma unroll
            for (int c = 0; c < HCHUNKS; c++)
                sum += g_part[((b * HEAVY_PER_B + r) * HCHUNKS + c) * Dd + col];
            int i = bm + 1 + r;
            int deg = g_off[i + 1] - g_off[i];
            g_agg[i * Dd + col] = sum / (float)deg;
        }
        __syncthreads();
    }

    unsigned long long acc[8][4];
#pragma unroll
    for (int i = 0; i < 8; i++)
#pragma unroll
        for (int j = 0; j < 4; j++) acc[i][j] = 0ull;

    // load assignments
    const int mA = tid >> 1;          // 0..63 (A row)
    const int hA = tid & 1;           // 0/1: cols hA*8 .. hA*8+7 (of 16)
    const int rB = tid >> 3;          // 0..15 (B row)
    const int cB = (tid & 7) * 16;    // B col base (16 floats)

    // tile it (0..15): pass = it>>3, k0 = (it&7)*16
    // --- prologue: tile 0 into buffer 0 ---
    {
        const float* ap = &g_agg[(bm + mA) * Dd + hA * 8];
        float4 v0 = *(const float4*)(ap);
        float4 v1 = *(const float4*)(ap + 4);
        int kb = hA * 8;
        As[0][kb + 0][mA] = v0.x;
        As[0][kb + 1][mA] = v0.y;
        As[0][kb + 2][mA] = v0.z;
        As[0][kb + 3][mA] = v0.w;
        As[0][kb + 4][mA] = v1.x;
        As[0][kb + 5][mA] = v1.y;
        As[0][kb + 6][mA] = v1.z;
        As[0][kb + 7][mA] = v1.w;
        uint32_t bdst = (uint32_t)__cvta_generic_to_shared(&Bs[0][rB][cB]);
        const float* wp = &W1[rB * Dd + cB];
#pragma unroll
        for (int j = 0; j < 4; j++)
            cp_async16(bdst + j * 16, wp + j * 4);
        cp_commit();
        cp_wait0();
    }
    __syncthreads();

#pragma unroll
    for (int it = 0; it < 16; it++) {
        const int cur = it & 1;
        const int nxt = cur ^ 1;

        // kick loads for tile it+1
        float4 a0, a1;
        if (it < 15) {
            const int nit = it + 1;
            const float* Ap = (nit >= 8) ? (const float*)g_h : (const float*)g_agg;
            const float* Wp = (nit >= 8) ? W2 : W1;
            const int k0 = (nit & 7) * 16;
            const float* ap = &Ap[(bm + mA) * Dd + k0 + hA * 8];
            a0 = *(const float4*)(ap);
            a1 = *(const float4*)(ap + 4);
            uint32_t bdst = (uint32_t)__cvta_generic_to_shared(&Bs[nxt][rB][cB]);
            const float* wp = &Wp[(k0 + rB) * Dd + cB];
#pragma unroll
            for (int j = 0; j < 4; j++)
                cp_async16(bdst + j * 16, wp + j * 4);
            cp_commit();
        }

        // compute tile it
#pragma unroll
        for (int kk = 0; kk < 16; kk++) {
            float4 af0 = *(const float4*)&As[cur][kk][tm];
            float4 af1 = *(const float4*)&As[cur][kk][tm + 4];
            ulonglong2 b01 = *(const ulonglong2*)&Bs[cur][kk][tn];
            ulonglong2 b23 = *(const ulonglong2*)&Bs[cur][kk][tn + 4];
            unsigned long long ap[8];
            ap[0] = pack2s(af0.x); ap[1] = pack2s(af0.y);
            ap[2] = pack2s(af0.z); ap[3] = pack2s(af0.w);
            ap[4] = pack2s(af1.x); ap[5] = pack2s(af1.y);
            ap[6] = pack2s(af1.z); ap[7] = pack2s(af1.w);
            unsigned long long bp[4] = {b01.x, b01.y, b23.x, b23.y};
#pragma unroll
            for (int i = 0; i < 8; i++) {
                ffma2(acc[i][0], ap[i], bp[0]);
                ffma2(acc[i][1], ap[i], bp[1]);
                ffma2(acc[i][2], ap[i], bp[2]);
                ffma2(acc[i][3], ap[i], bp[3]);
            }
        }

        // stage A for tile it+1, drain B cp.async, flip
        if (it < 15) {
            int kb = hA * 8;
            As[nxt][kb + 0][mA] = a0.x;
            As[nxt][kb + 1][mA] = a0.y;
            As[nxt][kb + 2][mA] = a0.z;
            As[nxt][kb + 3][mA] = a0.w;
            As[nxt][kb + 4][mA] = a1.x;
            As[nxt][kb + 5][mA] = a1.y;
            As[nxt][kb + 6][mA] = a1.z;
            As[nxt][kb + 7][mA] = a1.w;
            cp_wait0();
        }
        __syncthreads();
    }

    // Epilogue
    float bb[8], gg[8], be[8];
#pragma unroll
    for (int j = 0; j < 8; j++) bb[j] = bias[tn + j];
    if (FUSE) {
#pragma unroll
        for (int j = 0; j < 8; j++) { gg[j] = gamma[tn + j]; be[j] = beta[tn + j]; }
    }
#pragma unroll
    for (int i = 0; i < 8; i++) {
        int row = bm + tm + i;
        float4 x0 = *(const float4*)&X[row * Dd + tn];
        float4 x1 = *(const float4*)&X[row * Dd + tn + 4];
        float xv[8] = {x0.x, x0.y, x0.z, x0.w, x1.x, x1.y, x1.z, x1.w};
#pragma unroll
        for (int j = 0; j < 4; j++) {
            float lo, hi;
            unpack2(acc[i][j], lo, hi);
            xv[2*j]   += lo + bb[2*j];
            xv[2*j+1] += hi + bb[2*j+1];
        }
        x0 = make_float4(xv[0], xv[1], xv[2], xv[3]);
        x1 = make_float4(xv[4], xv[5], xv[6], xv[7]);
        *(float4*)&X[row * Dd + tn]     = x0;
        *(float4*)&X[row * Dd + tn + 4] = x1;
        if (FUSE) {
            float s = 0.f, s2 = 0.f;
#pragma unroll
            for (int j = 0; j < 8; j++) { s += xv[j]; s2 += xv[j] * xv[j]; }
#pragma unroll
            for (int o = 1; o <= 8; o <<= 1) {
                s  += __shfl_xor_sync(0xffffffffu, s, o);
                s2 += __shfl_xor_sync(0xffffffffu, s2, o);
            }
            float mu  = s * (1.0f / 128.0f);
            float var = s2 * (1.0f / 128.0f) - mu * mu;
            float rs  = rsqrtf(var + 1e-5f);
            float hv[8];
#pragma unroll
            for (int j = 0; j < 8; j++) {
                float t = (xv[j] - mu) * rs * gg[j] + be[j];
                hv[j] = 0.5f * t * (1.0f + erff(t * 0.70710678118654752f));
            }
            *(float4*)&g_h[row * Dd + tn]     = make_float4(hv[0], hv[1], hv[2], hv[3]);
            *(float4*)&g_h[row * Dd + tn + 4] = make_float4(hv[4], hv[5], hv[6], hv[7]);
        }
    }
}

// ---------------------------------------------------------------------------
extern "C" void kernel_launch(void* const* d_in, const int* in_sizes, int n_in,
                              void* d_out, int out_size) {
    const float* elements = (const float*)d_in[0];
    const float* ln_gamma = (const float*)d_in[1];
    const float* ln_beta  = (const float*)d_in[2];
    const float* w_nei    = (const float*)d_in[3];
    const float* b_nei    = (const float*)d_in[4];
    const float* w_root   = (const float*)d_in[5];
    const int*   edges    = (const int*)d_in[6];
    float* x = (float*)d_out;

    int E = in_sizes[6] / 2;
    const int* src = edges;
    const int* dst = edges + E;

    tree1off_kernel<<<256 + (E + 255) / 256, 256>>>(elements, dst, E);   // 1
    encx2_kernel<<<BN, Dd>>>(x, ln_gamma, ln_beta);                      // 2

    // layer 0
    agg_kernel<<<BN + HEAVY_W, Dd>>>(src);                               // 3
    gemm_kernel<true><<<BN / 64, 128>>>(w_nei, w_root, b_nei,
                                        ln_gamma + Dd, ln_beta + Dd, x); // 4 (profiled)

    // layer 1 (final — no fused LN)
    agg_kernel<<<BN + HEAVY_W, Dd>>>(src);                               // 5
    gemm_kernel<false><<<BN / 64, 128>>>(w_nei + Dd * Dd, w_root + Dd * Dd,
                                         b_nei + Dd, nullptr, nullptr, x); // 6
}